// round 1
// baseline (speedup 1.0000x reference)
#include <cuda_runtime.h>

#define N_NODES 100000
#define N_EDGES 3200000
#define F0 300
#define F1 128
#define F2 64

// ---- scratch (static device allocations; no cudaMalloc allowed) ----
__device__ int   g_deg[N_NODES];
__device__ float g_dinv[N_NODES];
__device__ float g_y1  [(size_t)N_NODES * F1];
__device__ float g_agg1[(size_t)N_NODES * F1];   // reused as h after relu
__device__ float g_y2  [(size_t)N_NODES * F2];
__device__ float g_agg2[(size_t)N_NODES * F2];

// ---------------- degree / norm ----------------
__global__ void k_init_deg() {
    int i = blockIdx.x * blockDim.x + threadIdx.x;
    if (i < N_NODES) g_deg[i] = 1;   // self-loop
}

__global__ void k_count(const int* __restrict__ dst) {
    int i = blockIdx.x * blockDim.x + threadIdx.x;
    if (i < N_EDGES) atomicAdd(&g_deg[dst[i]], 1);
}

__global__ void k_dinv() {
    int i = blockIdx.x * blockDim.x + threadIdx.x;
    if (i < N_NODES) g_dinv[i] = rsqrtf((float)g_deg[i]);
}

// ---------------- GEMM 1: y1 = dinv * (x @ W1), agg1 = y1 ----------------
// BM=64, BN=128 (full width), BK=20 (300 = 15*20), 256 threads,
// thread microtile 8 rows x 4 cols.
__global__ void k_gemm1(const float* __restrict__ x, const float* __restrict__ W) {
    __shared__ float As[20][64];
    __shared__ float Bs[20][128];
    const int tid = threadIdx.x;
    const int tx = tid & 31;      // col group -> cols tx*4 .. tx*4+3
    const int ty = tid >> 5;      // row group -> rows ty*8 .. ty*8+7
    const int row0 = blockIdx.x * 64;

    float acc[8][4];
#pragma unroll
    for (int i = 0; i < 8; i++)
#pragma unroll
        for (int j = 0; j < 4; j++) acc[i][j] = 0.f;

    for (int k0 = 0; k0 < F0; k0 += 20) {
        // A tile: 64x20, 5 elems/thread (thread covers 5 consecutive k of a row)
#pragma unroll
        for (int i = 0; i < 5; i++) {
            int idx = tid * 5 + i;
            int m = idx / 20, k = idx % 20;
            int r = row0 + m;
            As[k][m] = (r < N_NODES) ? x[(size_t)r * F0 + k0 + k] : 0.f;
        }
        // B tile: 20x128, 10 elems/thread, fully coalesced
#pragma unroll
        for (int i = 0; i < 10; i++) {
            int idx = tid + i * 256;
            int k = idx >> 7, f = idx & 127;
            Bs[k][f] = W[(size_t)(k0 + k) * F1 + f];
        }
        __syncthreads();
#pragma unroll
        for (int k = 0; k < 20; k++) {
            float4 bv = *(const float4*)&Bs[k][tx * 4];
            float4 a0 = *(const float4*)&As[k][ty * 8];
            float4 a1 = *(const float4*)&As[k][ty * 8 + 4];
            float a[8] = {a0.x, a0.y, a0.z, a0.w, a1.x, a1.y, a1.z, a1.w};
            float b[4] = {bv.x, bv.y, bv.z, bv.w};
#pragma unroll
            for (int i = 0; i < 8; i++)
#pragma unroll
                for (int j = 0; j < 4; j++) acc[i][j] = fmaf(a[i], b[j], acc[i][j]);
        }
        __syncthreads();
    }
#pragma unroll
    for (int i = 0; i < 8; i++) {
        int r = row0 + ty * 8 + i;
        if (r < N_NODES) {
            float s = g_dinv[r];
            float4 v = make_float4(acc[i][0] * s, acc[i][1] * s, acc[i][2] * s, acc[i][3] * s);
            size_t o = ((size_t)r * F1 + tx * 4) >> 2;
            ((float4*)g_y1)[o]   = v;
            ((float4*)g_agg1)[o] = v;   // self-loop term pre-seeded
        }
    }
}

// ---------------- scatter 1: agg1[dst] += y1[src], warp per edge ----------------
__global__ void k_scatter1(const int* __restrict__ src, const int* __restrict__ dst) {
    int e = blockIdx.x * 8 + (threadIdx.x >> 5);
    if (e >= N_EDGES) return;
    int lane = threadIdx.x & 31;
    int s = src[e];
    int d = dst[e];
    float4 v = ((const float4*)(g_y1 + (size_t)s * F1))[lane];
    float* a = g_agg1 + (size_t)d * F1 + lane * 4;
    atomicAdd(a + 0, v.x);
    atomicAdd(a + 1, v.y);
    atomicAdd(a + 2, v.z);
    atomicAdd(a + 3, v.w);
}

// ---------------- h = relu(dinv*agg1 + b1), in place ----------------
__global__ void k_bias_relu(const float* __restrict__ b) {
    size_t i = (size_t)blockIdx.x * blockDim.x + threadIdx.x;  // over N*32 float4
    if (i >= (size_t)N_NODES * (F1 / 4)) return;
    int row = (int)(i >> 5);
    int c = (int)(i & 31);
    float s = g_dinv[row];
    float4 v = ((float4*)g_agg1)[i];
    float4 bb = ((const float4*)b)[c];
    v.x = fmaxf(fmaf(v.x, s, bb.x), 0.f);
    v.y = fmaxf(fmaf(v.y, s, bb.y), 0.f);
    v.z = fmaxf(fmaf(v.z, s, bb.z), 0.f);
    v.w = fmaxf(fmaf(v.w, s, bb.w), 0.f);
    ((float4*)g_agg1)[i] = v;
}

// ---------------- GEMM 2: y2 = dinv * (h @ W2), agg2 = y2 ----------------
// BM=64, BN=64, BK=16 (K=128), 256 threads, microtile 4x4.
__global__ void k_gemm2(const float* __restrict__ W) {
    __shared__ float As[16][64];
    __shared__ float Bs[16][64];
    const int tid = threadIdx.x;
    const int tx = tid & 15;    // cols tx*4
    const int ty = tid >> 4;    // rows ty*4
    const int row0 = blockIdx.x * 64;

    float acc[4][4];
#pragma unroll
    for (int i = 0; i < 4; i++)
#pragma unroll
        for (int j = 0; j < 4; j++) acc[i][j] = 0.f;

    for (int k0 = 0; k0 < F1; k0 += 16) {
        // A tile 64x16, float4 per thread
        {
            int m = tid >> 2;
            int k = (tid & 3) * 4;
            int r = row0 + m;
            float4 v = (r < N_NODES)
                ? *(const float4*)&g_agg1[(size_t)r * F1 + k0 + k]
                : make_float4(0.f, 0.f, 0.f, 0.f);
            As[k][m] = v.x; As[k + 1][m] = v.y; As[k + 2][m] = v.z; As[k + 3][m] = v.w;
        }
        // B tile 16x64
#pragma unroll
        for (int i = 0; i < 4; i++) {
            int idx = tid + i * 256;
            Bs[idx >> 6][idx & 63] = W[(size_t)(k0 + (idx >> 6)) * F2 + (idx & 63)];
        }
        __syncthreads();
#pragma unroll
        for (int k = 0; k < 16; k++) {
            float4 av = *(const float4*)&As[k][ty * 4];
            float4 bv = *(const float4*)&Bs[k][tx * 4];
            float a[4] = {av.x, av.y, av.z, av.w};
            float b[4] = {bv.x, bv.y, bv.z, bv.w};
#pragma unroll
            for (int i = 0; i < 4; i++)
#pragma unroll
                for (int j = 0; j < 4; j++) acc[i][j] = fmaf(a[i], b[j], acc[i][j]);
        }
        __syncthreads();
    }
#pragma unroll
    for (int i = 0; i < 4; i++) {
        int r = row0 + ty * 4 + i;
        if (r < N_NODES) {
            float s = g_dinv[r];
            float4 v = make_float4(acc[i][0] * s, acc[i][1] * s, acc[i][2] * s, acc[i][3] * s);
            size_t o = ((size_t)r * F2 + tx * 4) >> 2;
            ((float4*)g_y2)[o]   = v;
            ((float4*)g_agg2)[o] = v;
        }
    }
}

// ---------------- scatter 2: agg2[dst] += y2[src] ----------------
__global__ void k_scatter2(const int* __restrict__ src, const int* __restrict__ dst) {
    int e = blockIdx.x * 8 + (threadIdx.x >> 5);
    if (e >= N_EDGES) return;
    int lane = threadIdx.x & 31;
    int s = src[e];
    int d = dst[e];
    float2 v = ((const float2*)(g_y2 + (size_t)s * F2))[lane];
    float* a = g_agg2 + (size_t)d * F2 + lane * 2;
    atomicAdd(a + 0, v.x);
    atomicAdd(a + 1, v.y);
}

// ---------------- out = dinv*agg2 + b2 ----------------
__global__ void k_out(const float* __restrict__ b, float* __restrict__ out) {
    size_t i = (size_t)blockIdx.x * blockDim.x + threadIdx.x;  // over N*16 float4
    if (i >= (size_t)N_NODES * (F2 / 4)) return;
    int row = (int)(i >> 4);
    int c = (int)(i & 15);
    float s = g_dinv[row];
    float4 v = ((float4*)g_agg2)[i];
    float4 bb = ((const float4*)b)[c];
    v.x = fmaf(v.x, s, bb.x);
    v.y = fmaf(v.y, s, bb.y);
    v.z = fmaf(v.z, s, bb.z);
    v.w = fmaf(v.w, s, bb.w);
    ((float4*)out)[i] = v;
}

extern "C" void kernel_launch(void* const* d_in, const int* in_sizes, int n_in,
                              void* d_out, int out_size) {
    const float* x   = (const float*)d_in[0];
    const int*   ei  = (const int*)d_in[1];
    const float* W1  = (const float*)d_in[2];
    const float* b1  = (const float*)d_in[3];
    const float* W2  = (const float*)d_in[4];
    const float* b2  = (const float*)d_in[5];
    float*       out = (float*)d_out;

    const int* src = ei;             // edge_index[0]
    const int* dst = ei + N_EDGES;   // edge_index[1]

    k_init_deg<<<(N_NODES + 255) / 256, 256>>>();
    k_count<<<(N_EDGES + 255) / 256, 256>>>(dst);
    k_dinv<<<(N_NODES + 255) / 256, 256>>>();

    k_gemm1<<<(N_NODES + 63) / 64, 256>>>(x, W1);
    k_scatter1<<<(N_EDGES + 7) / 8, 256>>>(src, dst);
    k_bias_relu<<<(N_NODES * (F1 / 4) + 255) / 256, 256>>>(b1);

    k_gemm2<<<(N_NODES + 63) / 64, 256>>>(W2);
    k_scatter2<<<(N_EDGES + 7) / 8, 256>>>(src, dst);
    k_out<<<(N_NODES * (F2 / 4) + 255) / 256, 256>>>(b2, out);
}

// round 2
// speedup vs baseline: 3.0447x; 3.0447x over previous
#include <cuda_runtime.h>

#define N_NODES 100000
#define N_EDGES 3200000
#define F0 300
#define F1 128
#define F2 64

#define SCAN_B 1024
#define N_SCANBLK ((N_NODES + SCAN_B - 1) / SCAN_B)   // 98

// ---- scratch (static device allocations; no cudaMalloc allowed) ----
__device__ int   g_deg[N_NODES];          // in-degree (edges only, no self loop)
__device__ int   g_off[N_NODES + 1];      // CSR offsets by dst
__device__ int   g_cur[N_NODES];          // fill cursors
__device__ int   g_csr[N_EDGES];          // src ids grouped by dst
__device__ int   g_bsum[N_SCANBLK];
__device__ int   g_bpre[N_SCANBLK];
__device__ float g_dinv[N_NODES];
__device__ float g_y1[(size_t)N_NODES * F1];
__device__ float g_h [(size_t)N_NODES * F1];
__device__ float g_y2[(size_t)N_NODES * F2];

// ---------------- degree ----------------
__global__ void k_zero_deg() {
    int i = blockIdx.x * blockDim.x + threadIdx.x;
    if (i < N_NODES) g_deg[i] = 0;
}

__global__ void k_count(const int* __restrict__ dst) {
    int i = blockIdx.x * blockDim.x + threadIdx.x;
    if (i < N_EDGES) atomicAdd(&g_deg[dst[i]], 1);
}

// ---------------- scan (3 phases) ----------------
__global__ void k_scan1() {
    __shared__ int sh[SCAN_B];
    int tid = threadIdx.x;
    int gid = blockIdx.x * SCAN_B + tid;
    int v = (gid < N_NODES) ? g_deg[gid] : 0;
    sh[tid] = v;
    __syncthreads();
#pragma unroll
    for (int off = 1; off < SCAN_B; off <<= 1) {
        int t = (tid >= off) ? sh[tid - off] : 0;
        __syncthreads();
        sh[tid] += t;
        __syncthreads();
    }
    if (gid < N_NODES) g_off[gid] = sh[tid] - v;          // exclusive within block
    if (tid == SCAN_B - 1) g_bsum[blockIdx.x] = sh[tid];  // block total
}

__global__ void k_scan2() {   // single block of 128 threads over 98 sums
    __shared__ int sh[128];
    int tid = threadIdx.x;
    int v = (tid < N_SCANBLK) ? g_bsum[tid] : 0;
    sh[tid] = v;
    __syncthreads();
#pragma unroll
    for (int off = 1; off < 128; off <<= 1) {
        int t = (tid >= off) ? sh[tid - off] : 0;
        __syncthreads();
        sh[tid] += t;
        __syncthreads();
    }
    if (tid < N_SCANBLK) g_bpre[tid] = sh[tid] - v;       // exclusive block prefix
}

__global__ void k_scan3() {   // add block prefixes; init cursors; dinv
    int gid = blockIdx.x * SCAN_B + threadIdx.x;
    if (gid < N_NODES) {
        int o = g_off[gid] + g_bpre[blockIdx.x];
        g_off[gid] = o;
        g_cur[gid] = o;
        g_dinv[gid] = rsqrtf((float)(g_deg[gid] + 1));    // +1 self loop
    }
    if (gid == 0) g_off[N_NODES] = N_EDGES;
}

// ---------------- CSR fill ----------------
__global__ void k_fill(const int* __restrict__ src, const int* __restrict__ dst) {
    int i = blockIdx.x * blockDim.x + threadIdx.x;
    if (i < N_EDGES) {
        int pos = atomicAdd(&g_cur[dst[i]], 1);
        g_csr[pos] = src[i];
    }
}

// ---------------- GEMM 1: y1 = dinv * (x @ W1) ----------------
__global__ void k_gemm1(const float* __restrict__ x, const float* __restrict__ W) {
    __shared__ float As[20][64];
    __shared__ float Bs[20][128];
    const int tid = threadIdx.x;
    const int tx = tid & 31;      // cols tx*4
    const int ty = tid >> 5;      // rows ty*8
    const int row0 = blockIdx.x * 64;

    float acc[8][4];
#pragma unroll
    for (int i = 0; i < 8; i++)
#pragma unroll
        for (int j = 0; j < 4; j++) acc[i][j] = 0.f;

    for (int k0 = 0; k0 < F0; k0 += 20) {
#pragma unroll
        for (int i = 0; i < 5; i++) {
            int idx = tid * 5 + i;
            int m = idx / 20, k = idx % 20;
            int r = row0 + m;
            As[k][m] = (r < N_NODES) ? x[(size_t)r * F0 + k0 + k] : 0.f;
        }
#pragma unroll
        for (int i = 0; i < 10; i++) {
            int idx = tid + i * 256;
            int k = idx >> 7, f = idx & 127;
            Bs[k][f] = W[(size_t)(k0 + k) * F1 + f];
        }
        __syncthreads();
#pragma unroll
        for (int k = 0; k < 20; k++) {
            float4 bv = *(const float4*)&Bs[k][tx * 4];
            float4 a0 = *(const float4*)&As[k][ty * 8];
            float4 a1 = *(const float4*)&As[k][ty * 8 + 4];
            float a[8] = {a0.x, a0.y, a0.z, a0.w, a1.x, a1.y, a1.z, a1.w};
            float b[4] = {bv.x, bv.y, bv.z, bv.w};
#pragma unroll
            for (int i = 0; i < 8; i++)
#pragma unroll
                for (int j = 0; j < 4; j++) acc[i][j] = fmaf(a[i], b[j], acc[i][j]);
        }
        __syncthreads();
    }
#pragma unroll
    for (int i = 0; i < 8; i++) {
        int r = row0 + ty * 8 + i;
        if (r < N_NODES) {
            float s = g_dinv[r];
            ((float4*)g_y1)[((size_t)r * F1 + tx * 4) >> 2] =
                make_float4(acc[i][0] * s, acc[i][1] * s, acc[i][2] * s, acc[i][3] * s);
        }
    }
}

// ---------------- agg 1: h = relu(dinv[d]*(y1[d] + sum y1[src]) + b1) ----------------
// one warp per dst node; lane covers 4 of 128 feats.
__global__ void k_agg1(const float* __restrict__ b) {
    int d = blockIdx.x * 8 + (threadIdx.x >> 5);
    if (d >= N_NODES) return;
    int lane = threadIdx.x & 31;
    const float4* Y = (const float4*)g_y1;

    float4 a0 = Y[(size_t)d * 32 + lane];   // self loop
    float4 a1 = make_float4(0.f, 0.f, 0.f, 0.f);
    float4 a2 = make_float4(0.f, 0.f, 0.f, 0.f);
    float4 a3 = make_float4(0.f, 0.f, 0.f, 0.f);

    int j = g_off[d], end = g_off[d + 1];
    for (; j + 4 <= end; j += 4) {
        int s0 = g_csr[j], s1 = g_csr[j + 1], s2 = g_csr[j + 2], s3 = g_csr[j + 3];
        float4 v0 = Y[(size_t)s0 * 32 + lane];
        float4 v1 = Y[(size_t)s1 * 32 + lane];
        float4 v2 = Y[(size_t)s2 * 32 + lane];
        float4 v3 = Y[(size_t)s3 * 32 + lane];
        a0.x += v0.x; a0.y += v0.y; a0.z += v0.z; a0.w += v0.w;
        a1.x += v1.x; a1.y += v1.y; a1.z += v1.z; a1.w += v1.w;
        a2.x += v2.x; a2.y += v2.y; a2.z += v2.z; a2.w += v2.w;
        a3.x += v3.x; a3.y += v3.y; a3.z += v3.z; a3.w += v3.w;
    }
    for (; j < end; j++) {
        float4 v = Y[(size_t)g_csr[j] * 32 + lane];
        a0.x += v.x; a0.y += v.y; a0.z += v.z; a0.w += v.w;
    }
    float4 acc = make_float4(a0.x + a1.x + a2.x + a3.x,
                             a0.y + a1.y + a2.y + a3.y,
                             a0.z + a1.z + a2.z + a3.z,
                             a0.w + a1.w + a2.w + a3.w);
    float s = g_dinv[d];
    float4 bb = ((const float4*)b)[lane];
    acc.x = fmaxf(fmaf(acc.x, s, bb.x), 0.f);
    acc.y = fmaxf(fmaf(acc.y, s, bb.y), 0.f);
    acc.z = fmaxf(fmaf(acc.z, s, bb.z), 0.f);
    acc.w = fmaxf(fmaf(acc.w, s, bb.w), 0.f);
    ((float4*)g_h)[(size_t)d * 32 + lane] = acc;
}

// ---------------- GEMM 2: y2 = dinv * (h @ W2) ----------------
__global__ void k_gemm2(const float* __restrict__ W) {
    __shared__ float As[16][64];
    __shared__ float Bs[16][64];
    const int tid = threadIdx.x;
    const int tx = tid & 15;
    const int ty = tid >> 4;
    const int row0 = blockIdx.x * 64;

    float acc[4][4];
#pragma unroll
    for (int i = 0; i < 4; i++)
#pragma unroll
        for (int j = 0; j < 4; j++) acc[i][j] = 0.f;

    for (int k0 = 0; k0 < F1; k0 += 16) {
        {
            int m = tid >> 2;
            int k = (tid & 3) * 4;
            int r = row0 + m;
            float4 v = (r < N_NODES)
                ? *(const float4*)&g_h[(size_t)r * F1 + k0 + k]
                : make_float4(0.f, 0.f, 0.f, 0.f);
            As[k][m] = v.x; As[k + 1][m] = v.y; As[k + 2][m] = v.z; As[k + 3][m] = v.w;
        }
#pragma unroll
        for (int i = 0; i < 4; i++) {
            int idx = tid + i * 256;
            Bs[idx >> 6][idx & 63] = W[(size_t)(k0 + (idx >> 6)) * F2 + (idx & 63)];
        }
        __syncthreads();
#pragma unroll
        for (int k = 0; k < 16; k++) {
            float4 av = *(const float4*)&As[k][ty * 4];
            float4 bv = *(const float4*)&Bs[k][tx * 4];
            float a[4] = {av.x, av.y, av.z, av.w};
            float b[4] = {bv.x, bv.y, bv.z, bv.w};
#pragma unroll
            for (int i = 0; i < 4; i++)
#pragma unroll
                for (int j = 0; j < 4; j++) acc[i][j] = fmaf(a[i], b[j], acc[i][j]);
        }
        __syncthreads();
    }
#pragma unroll
    for (int i = 0; i < 4; i++) {
        int r = row0 + ty * 4 + i;
        if (r < N_NODES) {
            float s = g_dinv[r];
            ((float4*)g_y2)[((size_t)r * F2 + tx * 4) >> 2] =
                make_float4(acc[i][0] * s, acc[i][1] * s, acc[i][2] * s, acc[i][3] * s);
        }
    }
}

// ---------------- agg 2: out = dinv[d]*(y2[d] + sum y2[src]) + b2 ----------------
// one warp per dst node; lane covers 2 of 64 feats.
__global__ void k_agg2(const float* __restrict__ b, float* __restrict__ out) {
    int d = blockIdx.x * 8 + (threadIdx.x >> 5);
    if (d >= N_NODES) return;
    int lane = threadIdx.x & 31;
    const float2* Y = (const float2*)g_y2;

    float2 a0 = Y[(size_t)d * 32 + lane];   // self loop
    float2 a1 = make_float2(0.f, 0.f);
    float2 a2 = make_float2(0.f, 0.f);
    float2 a3 = make_float2(0.f, 0.f);

    int j = g_off[d], end = g_off[d + 1];
    for (; j + 4 <= end; j += 4) {
        int s0 = g_csr[j], s1 = g_csr[j + 1], s2 = g_csr[j + 2], s3 = g_csr[j + 3];
        float2 v0 = Y[(size_t)s0 * 32 + lane];
        float2 v1 = Y[(size_t)s1 * 32 + lane];
        float2 v2 = Y[(size_t)s2 * 32 + lane];
        float2 v3 = Y[(size_t)s3 * 32 + lane];
        a0.x += v0.x; a0.y += v0.y;
        a1.x += v1.x; a1.y += v1.y;
        a2.x += v2.x; a2.y += v2.y;
        a3.x += v3.x; a3.y += v3.y;
    }
    for (; j < end; j++) {
        float2 v = Y[(size_t)g_csr[j] * 32 + lane];
        a0.x += v.x; a0.y += v.y;
    }
    float2 acc = make_float2(a0.x + a1.x + a2.x + a3.x,
                             a0.y + a1.y + a2.y + a3.y);
    float s = g_dinv[d];
    float2 bb = ((const float2*)b)[lane];
    acc.x = fmaf(acc.x, s, bb.x);
    acc.y = fmaf(acc.y, s, bb.y);
    ((float2*)out)[(size_t)d * 32 + lane] = acc;
}

extern "C" void kernel_launch(void* const* d_in, const int* in_sizes, int n_in,
                              void* d_out, int out_size) {
    const float* x   = (const float*)d_in[0];
    const int*   ei  = (const int*)d_in[1];
    const float* W1  = (const float*)d_in[2];
    const float* b1  = (const float*)d_in[3];
    const float* W2  = (const float*)d_in[4];
    const float* b2  = (const float*)d_in[5];
    float*       out = (float*)d_out;

    const int* src = ei;             // edge_index[0]
    const int* dst = ei + N_EDGES;   // edge_index[1]

    // CSR build (by dst)
    k_zero_deg<<<(N_NODES + 255) / 256, 256>>>();
    k_count<<<(N_EDGES + 255) / 256, 256>>>(dst);
    k_scan1<<<N_SCANBLK, SCAN_B>>>();
    k_scan2<<<1, 128>>>();
    k_scan3<<<N_SCANBLK, SCAN_B>>>();
    k_fill<<<(N_EDGES + 255) / 256, 256>>>(src, dst);

    // Layer 1
    k_gemm1<<<(N_NODES + 63) / 64, 256>>>(x, W1);
    k_agg1<<<(N_NODES + 7) / 8, 256>>>(b1);

    // Layer 2
    k_gemm2<<<(N_NODES + 63) / 64, 256>>>(W2);
    k_agg2<<<(N_NODES + 7) / 8, 256>>>(b2, out);
}

// round 3
// speedup vs baseline: 3.2047x; 1.0525x over previous
#include <cuda_runtime.h>
#include <cuda_fp16.h>

#define N_NODES 100000
#define N_EDGES 3200000
#define F0 300
#define F1 128
#define F2 64

#define SCAN_B 1024
#define N_SCANBLK ((N_NODES + SCAN_B - 1) / SCAN_B)   // 98

// ---- scratch (static device allocations; no cudaMalloc allowed) ----
__device__ int    g_deg[N_NODES];
__device__ int    g_off[N_NODES + 1];
__device__ int    g_cur[N_NODES];
__device__ int    g_csr[N_EDGES];
__device__ int    g_bsum[N_SCANBLK];
__device__ int    g_bpre[N_SCANBLK];
__device__ float  g_dinv[N_NODES];
__device__ __half g_y1h[(size_t)N_NODES * F1];   // fp16 message rows, layer 1
__device__ float  g_h [(size_t)N_NODES * F1];    // fp32 hidden (GEMM2 input)
__device__ __half g_y2h[(size_t)N_NODES * F2];   // fp16 message rows, layer 2

// ---------------- degree ----------------
__global__ void k_zero_deg() {
    int i = blockIdx.x * blockDim.x + threadIdx.x;
    if (i < N_NODES) g_deg[i] = 0;
}

__global__ void k_count(const int* __restrict__ dst) {
    int i = blockIdx.x * blockDim.x + threadIdx.x;
    if (i < N_EDGES) atomicAdd(&g_deg[dst[i]], 1);
}

// ---------------- scan (3 phases) ----------------
__global__ void k_scan1() {
    __shared__ int sh[SCAN_B];
    int tid = threadIdx.x;
    int gid = blockIdx.x * SCAN_B + tid;
    int v = (gid < N_NODES) ? g_deg[gid] : 0;
    sh[tid] = v;
    __syncthreads();
#pragma unroll
    for (int off = 1; off < SCAN_B; off <<= 1) {
        int t = (tid >= off) ? sh[tid - off] : 0;
        __syncthreads();
        sh[tid] += t;
        __syncthreads();
    }
    if (gid < N_NODES) g_off[gid] = sh[tid] - v;
    if (tid == SCAN_B - 1) g_bsum[blockIdx.x] = sh[tid];
}

__global__ void k_scan2() {
    __shared__ int sh[128];
    int tid = threadIdx.x;
    int v = (tid < N_SCANBLK) ? g_bsum[tid] : 0;
    sh[tid] = v;
    __syncthreads();
#pragma unroll
    for (int off = 1; off < 128; off <<= 1) {
        int t = (tid >= off) ? sh[tid - off] : 0;
        __syncthreads();
        sh[tid] += t;
        __syncthreads();
    }
    if (tid < N_SCANBLK) g_bpre[tid] = sh[tid] - v;
}

__global__ void k_scan3() {
    int gid = blockIdx.x * SCAN_B + threadIdx.x;
    if (gid < N_NODES) {
        int o = g_off[gid] + g_bpre[blockIdx.x];
        g_off[gid] = o;
        g_cur[gid] = o;
        g_dinv[gid] = rsqrtf((float)(g_deg[gid] + 1));
    }
    if (gid == 0) g_off[N_NODES] = N_EDGES;
}

// ---------------- CSR fill ----------------
__global__ void k_fill(const int* __restrict__ src, const int* __restrict__ dst) {
    int i = blockIdx.x * blockDim.x + threadIdx.x;
    if (i < N_EDGES) {
        int pos = atomicAdd(&g_cur[dst[i]], 1);
        g_csr[pos] = src[i];
    }
}

// ---------------- GEMM 1: y1h = half(dinv * (x @ W1)) ----------------
__global__ void k_gemm1(const float* __restrict__ x, const float* __restrict__ W) {
    __shared__ float As[20][64];
    __shared__ float Bs[20][128];
    const int tid = threadIdx.x;
    const int tx = tid & 31;      // cols tx*4
    const int ty = tid >> 5;      // rows ty*8
    const int row0 = blockIdx.x * 64;

    float acc[8][4];
#pragma unroll
    for (int i = 0; i < 8; i++)
#pragma unroll
        for (int j = 0; j < 4; j++) acc[i][j] = 0.f;

    for (int k0 = 0; k0 < F0; k0 += 20) {
#pragma unroll
        for (int i = 0; i < 5; i++) {
            int idx = tid * 5 + i;
            int m = idx / 20, k = idx % 20;
            int r = row0 + m;
            As[k][m] = (r < N_NODES) ? x[(size_t)r * F0 + k0 + k] : 0.f;
        }
#pragma unroll
        for (int i = 0; i < 10; i++) {
            int idx = tid + i * 256;
            int k = idx >> 7, f = idx & 127;
            Bs[k][f] = W[(size_t)(k0 + k) * F1 + f];
        }
        __syncthreads();
#pragma unroll
        for (int k = 0; k < 20; k++) {
            float4 bv = *(const float4*)&Bs[k][tx * 4];
            float4 a0 = *(const float4*)&As[k][ty * 8];
            float4 a1 = *(const float4*)&As[k][ty * 8 + 4];
            float a[8] = {a0.x, a0.y, a0.z, a0.w, a1.x, a1.y, a1.z, a1.w};
            float b[4] = {bv.x, bv.y, bv.z, bv.w};
#pragma unroll
            for (int i = 0; i < 8; i++)
#pragma unroll
                for (int j = 0; j < 4; j++) acc[i][j] = fmaf(a[i], b[j], acc[i][j]);
        }
        __syncthreads();
    }
#pragma unroll
    for (int i = 0; i < 8; i++) {
        int r = row0 + ty * 8 + i;
        if (r < N_NODES) {
            float s = g_dinv[r];
            __half2 p0 = __floats2half2_rn(acc[i][0] * s, acc[i][1] * s);
            __half2 p1 = __floats2half2_rn(acc[i][2] * s, acc[i][3] * s);
            float2 pk;
            pk.x = __uint_as_float(*(unsigned int*)&p0);
            pk.y = __uint_as_float(*(unsigned int*)&p1);
            ((float2*)g_y1h)[((size_t)r * F1 + tx * 4) >> 2] = pk;
        }
    }
}

// ---------------- agg 1: h = relu(dinv[d]*(y1[d] + sum y1[src]) + b1) ----------------
// warp per dst node; lane covers 4 halfs (8B) of the 256B row.
__global__ void k_agg1(const float* __restrict__ b) {
    int d = blockIdx.x * 8 + (threadIdx.x >> 5);
    if (d >= N_NODES) return;
    int lane = threadIdx.x & 31;
    const float2* Y = (const float2*)g_y1h;   // 32 float2 per row

    float ax[4] = {0.f, 0.f, 0.f, 0.f};
    {
        float2 r = Y[(size_t)d * 32 + lane];  // self loop
        float2 f0 = __half22float2(*(__half2*)&r.x);
        float2 f1 = __half22float2(*(__half2*)&r.y);
        ax[0] = f0.x; ax[1] = f0.y; ax[2] = f1.x; ax[3] = f1.y;
    }
    float ay[4] = {0.f, 0.f, 0.f, 0.f};
    float az[4] = {0.f, 0.f, 0.f, 0.f};
    float aw[4] = {0.f, 0.f, 0.f, 0.f};

    int j = g_off[d], end = g_off[d + 1];
    for (; j + 4 <= end; j += 4) {
        int s0 = g_csr[j], s1 = g_csr[j + 1], s2 = g_csr[j + 2], s3 = g_csr[j + 3];
        float2 r0 = Y[(size_t)s0 * 32 + lane];
        float2 r1 = Y[(size_t)s1 * 32 + lane];
        float2 r2 = Y[(size_t)s2 * 32 + lane];
        float2 r3 = Y[(size_t)s3 * 32 + lane];
        float2 f;
        f = __half22float2(*(__half2*)&r0.x); ax[0] += f.x; ax[1] += f.y;
        f = __half22float2(*(__half2*)&r0.y); ax[2] += f.x; ax[3] += f.y;
        f = __half22float2(*(__half2*)&r1.x); ay[0] += f.x; ay[1] += f.y;
        f = __half22float2(*(__half2*)&r1.y); ay[2] += f.x; ay[3] += f.y;
        f = __half22float2(*(__half2*)&r2.x); az[0] += f.x; az[1] += f.y;
        f = __half22float2(*(__half2*)&r2.y); az[2] += f.x; az[3] += f.y;
        f = __half22float2(*(__half2*)&r3.x); aw[0] += f.x; aw[1] += f.y;
        f = __half22float2(*(__half2*)&r3.y); aw[2] += f.x; aw[3] += f.y;
    }
    for (; j < end; j++) {
        float2 r = Y[(size_t)g_csr[j] * 32 + lane];
        float2 f;
        f = __half22float2(*(__half2*)&r.x); ax[0] += f.x; ax[1] += f.y;
        f = __half22float2(*(__half2*)&r.y); ax[2] += f.x; ax[3] += f.y;
    }
#pragma unroll
    for (int i = 0; i < 4; i++) ax[i] += ay[i] + az[i] + aw[i];

    float s = g_dinv[d];
    float4 bb = ((const float4*)b)[lane];
    float4 o;
    o.x = fmaxf(fmaf(ax[0], s, bb.x), 0.f);
    o.y = fmaxf(fmaf(ax[1], s, bb.y), 0.f);
    o.z = fmaxf(fmaf(ax[2], s, bb.z), 0.f);
    o.w = fmaxf(fmaf(ax[3], s, bb.w), 0.f);
    ((float4*)g_h)[(size_t)d * 32 + lane] = o;
}

// ---------------- GEMM 2: y2h = half(dinv * (h @ W2)) ----------------
__global__ void k_gemm2(const float* __restrict__ W) {
    __shared__ float As[16][64];
    __shared__ float Bs[16][64];
    const int tid = threadIdx.x;
    const int tx = tid & 15;
    const int ty = tid >> 4;
    const int row0 = blockIdx.x * 64;

    float acc[4][4];
#pragma unroll
    for (int i = 0; i < 4; i++)
#pragma unroll
        for (int j = 0; j < 4; j++) acc[i][j] = 0.f;

    for (int k0 = 0; k0 < F1; k0 += 16) {
        {
            int m = tid >> 2;
            int k = (tid & 3) * 4;
            int r = row0 + m;
            float4 v = (r < N_NODES)
                ? *(const float4*)&g_h[(size_t)r * F1 + k0 + k]
                : make_float4(0.f, 0.f, 0.f, 0.f);
            As[k][m] = v.x; As[k + 1][m] = v.y; As[k + 2][m] = v.z; As[k + 3][m] = v.w;
        }
#pragma unroll
        for (int i = 0; i < 4; i++) {
            int idx = tid + i * 256;
            Bs[idx >> 6][idx & 63] = W[(size_t)(k0 + (idx >> 6)) * F2 + (idx & 63)];
        }
        __syncthreads();
#pragma unroll
        for (int k = 0; k < 16; k++) {
            float4 av = *(const float4*)&As[k][ty * 4];
            float4 bv = *(const float4*)&Bs[k][tx * 4];
            float a[4] = {av.x, av.y, av.z, av.w};
            float b[4] = {bv.x, bv.y, bv.z, bv.w};
#pragma unroll
            for (int i = 0; i < 4; i++)
#pragma unroll
                for (int j = 0; j < 4; j++) acc[i][j] = fmaf(a[i], b[j], acc[i][j]);
        }
        __syncthreads();
    }
#pragma unroll
    for (int i = 0; i < 4; i++) {
        int r = row0 + ty * 4 + i;
        if (r < N_NODES) {
            float s = g_dinv[r];
            __half2 p0 = __floats2half2_rn(acc[i][0] * s, acc[i][1] * s);
            __half2 p1 = __floats2half2_rn(acc[i][2] * s, acc[i][3] * s);
            float2 pk;
            pk.x = __uint_as_float(*(unsigned int*)&p0);
            pk.y = __uint_as_float(*(unsigned int*)&p1);
            ((float2*)g_y2h)[((size_t)r * F2 + tx * 4) >> 2] = pk;
        }
    }
}

// ---------------- agg 2: out = dinv[d]*(y2[d] + sum y2[src]) + b2 ----------------
// warp per dst node; lane covers 2 halfs (4B) of the 128B row.
__global__ void k_agg2(const float* __restrict__ b, float* __restrict__ out) {
    int d = blockIdx.x * 8 + (threadIdx.x >> 5);
    if (d >= N_NODES) return;
    int lane = threadIdx.x & 31;
    const __half2* Y = (const __half2*)g_y2h;   // 32 half2 per row

    float2 a0 = __half22float2(Y[(size_t)d * 32 + lane]);  // self loop
    float2 a1 = make_float2(0.f, 0.f);
    float2 a2 = make_float2(0.f, 0.f);
    float2 a3 = make_float2(0.f, 0.f);

    int j = g_off[d], end = g_off[d + 1];
    for (; j + 4 <= end; j += 4) {
        int s0 = g_csr[j], s1 = g_csr[j + 1], s2 = g_csr[j + 2], s3 = g_csr[j + 3];
        float2 v0 = __half22float2(Y[(size_t)s0 * 32 + lane]);
        float2 v1 = __half22float2(Y[(size_t)s1 * 32 + lane]);
        float2 v2 = __half22float2(Y[(size_t)s2 * 32 + lane]);
        float2 v3 = __half22float2(Y[(size_t)s3 * 32 + lane]);
        a0.x += v0.x; a0.y += v0.y;
        a1.x += v1.x; a1.y += v1.y;
        a2.x += v2.x; a2.y += v2.y;
        a3.x += v3.x; a3.y += v3.y;
    }
    for (; j < end; j++) {
        float2 v = __half22float2(Y[(size_t)g_csr[j] * 32 + lane]);
        a0.x += v.x; a0.y += v.y;
    }
    float2 acc = make_float2(a0.x + a1.x + a2.x + a3.x,
                             a0.y + a1.y + a2.y + a3.y);
    float s = g_dinv[d];
    float2 bb = ((const float2*)b)[lane];
    acc.x = fmaf(acc.x, s, bb.x);
    acc.y = fmaf(acc.y, s, bb.y);
    ((float2*)out)[(size_t)d * 32 + lane] = acc;
}

extern "C" void kernel_launch(void* const* d_in, const int* in_sizes, int n_in,
                              void* d_out, int out_size) {
    const float* x   = (const float*)d_in[0];
    const int*   ei  = (const int*)d_in[1];
    const float* W1  = (const float*)d_in[2];
    const float* b1  = (const float*)d_in[3];
    const float* W2  = (const float*)d_in[4];
    const float* b2  = (const float*)d_in[5];
    float*       out = (float*)d_out;

    const int* src = ei;
    const int* dst = ei + N_EDGES;

    k_zero_deg<<<(N_NODES + 255) / 256, 256>>>();
    k_count<<<(N_EDGES + 255) / 256, 256>>>(dst);
    k_scan1<<<N_SCANBLK, SCAN_B>>>();
    k_scan2<<<1, 128>>>();
    k_scan3<<<N_SCANBLK, SCAN_B>>>();
    k_fill<<<(N_EDGES + 255) / 256, 256>>>(src, dst);

    k_gemm1<<<(N_NODES + 63) / 64, 256>>>(x, W1);
    k_agg1<<<(N_NODES + 7) / 8, 256>>>(b1);

    k_gemm2<<<(N_NODES + 63) / 64, 256>>>(W2);
    k_agg2<<<(N_NODES + 7) / 8, 256>>>(b2, out);
}

// round 4
// speedup vs baseline: 3.6151x; 1.1281x over previous
#include <cuda_runtime.h>
#include <cuda_fp16.h>

#define N_NODES 100000
#define N_EDGES 3200000
#define F0 300
#define F0P 304            // padded K for GEMM1
#define F1 128
#define F2 64

#define SCAN_B 1024
#define N_SCANBLK ((N_NODES + SCAN_B - 1) / SCAN_B)   // 98

// ---- scratch (static device allocations; no cudaMalloc allowed) ----
__device__ int    g_deg[N_NODES];
__device__ int    g_off[N_NODES + 1];
__device__ int    g_cur[N_NODES];
__device__ int    g_csr[N_EDGES];
__device__ int    g_bsum[N_SCANBLK];
__device__ int    g_bpre[N_SCANBLK];
__device__ float  g_dinv[N_NODES];
__device__ __half g_y1h[(size_t)N_NODES * F1];   // fp16 message rows, layer 1
__device__ float  g_h [(size_t)N_NODES * F1];    // fp32 hidden (GEMM2 input)
__device__ __half g_y2h[(size_t)N_NODES * F2];   // fp16 message rows, layer 2

// ---------------- degree ----------------
__global__ void k_zero_deg() {
    int i = blockIdx.x * blockDim.x + threadIdx.x;
    if (i < N_NODES) g_deg[i] = 0;
}

__global__ void k_count(const int* __restrict__ dst) {
    int i = blockIdx.x * blockDim.x + threadIdx.x;
    if (i < N_EDGES) atomicAdd(&g_deg[dst[i]], 1);
}

// ---------------- scan (3 phases) ----------------
__global__ void k_scan1() {
    __shared__ int sh[SCAN_B];
    int tid = threadIdx.x;
    int gid = blockIdx.x * SCAN_B + tid;
    int v = (gid < N_NODES) ? g_deg[gid] : 0;
    sh[tid] = v;
    __syncthreads();
#pragma unroll
    for (int off = 1; off < SCAN_B; off <<= 1) {
        int t = (tid >= off) ? sh[tid - off] : 0;
        __syncthreads();
        sh[tid] += t;
        __syncthreads();
    }
    if (gid < N_NODES) g_off[gid] = sh[tid] - v;
    if (tid == SCAN_B - 1) g_bsum[blockIdx.x] = sh[tid];
}

__global__ void k_scan2() {
    __shared__ int sh[128];
    int tid = threadIdx.x;
    int v = (tid < N_SCANBLK) ? g_bsum[tid] : 0;
    sh[tid] = v;
    __syncthreads();
#pragma unroll
    for (int off = 1; off < 128; off <<= 1) {
        int t = (tid >= off) ? sh[tid - off] : 0;
        __syncthreads();
        sh[tid] += t;
        __syncthreads();
    }
    if (tid < N_SCANBLK) g_bpre[tid] = sh[tid] - v;
}

__global__ void k_scan3() {
    int gid = blockIdx.x * SCAN_B + threadIdx.x;
    if (gid < N_NODES) {
        int o = g_off[gid] + g_bpre[blockIdx.x];
        g_off[gid] = o;
        g_cur[gid] = o;
        g_dinv[gid] = rsqrtf((float)(g_deg[gid] + 1));
    }
    if (gid == 0) g_off[N_NODES] = N_EDGES;
}

// ---------------- CSR fill ----------------
__global__ void k_fill(const int* __restrict__ src, const int* __restrict__ dst) {
    int i = blockIdx.x * blockDim.x + threadIdx.x;
    if (i < N_EDGES) {
        int pos = atomicAdd(&g_cur[dst[i]], 1);
        g_csr[pos] = src[i];
    }
}

// ---------------- helpers ----------------
__device__ __forceinline__ void split_store(__half* hi, __half* lo, float f) {
    __half h = __float2half_rn(f);
    *hi = h;
    *lo = __float2half_rn(f - __half2float(h));
}

#define MMA16816(D, A, B)                                                      \
    asm volatile(                                                              \
        "mma.sync.aligned.m16n8k16.row.col.f32.f16.f16.f32 "                   \
        "{%0,%1,%2,%3}, {%4,%5,%6,%7}, {%8,%9}, {%0,%1,%2,%3};"                \
        : "+f"((D)[0]), "+f"((D)[1]), "+f"((D)[2]), "+f"((D)[3])               \
        : "r"((A)[0]), "r"((A)[1]), "r"((A)[2]), "r"((A)[3]),                  \
          "r"((B)[0]), "r"((B)[1]))

// ---------------- GEMM 1 (HMMA, fp16 hi/lo split): y1h = half(dinv*(x@W1)) --
// BM=64, BN=128, BK=16, 8 warps in 4(M) x 2(N); warp tile 16x64.
__global__ __launch_bounds__(256) void k_gemm1(const float* __restrict__ x,
                                               const float* __restrict__ W) {
    __shared__ __half Ah[64][16], Al[64][16];
    __shared__ __half Bh[128][18], Bl[128][18];   // [n][k], padded

    const int tid  = threadIdx.x;
    const int warp = tid >> 5, lane = tid & 31;
    const int wm = warp >> 1, wn = warp & 1;
    const int gr = lane >> 2, ct = lane & 3;
    const int row0 = blockIdx.x * 64;

    float d[8][4];
#pragma unroll
    for (int i = 0; i < 8; i++)
#pragma unroll
        for (int j = 0; j < 4; j++) d[i][j] = 0.f;

    for (int k0 = 0; k0 < F0P; k0 += 16) {
        // ---- load A tile 64x16 (fp32 -> hi/lo fp16) ----
        {
            int r = tid >> 2;
            int c = (tid & 3) * 4;
            int grow = row0 + r;
            float4 v = make_float4(0.f, 0.f, 0.f, 0.f);
            if (grow < N_NODES) {
                if (k0 + 16 <= F0) {
                    v = *(const float4*)&x[(size_t)grow * F0 + k0 + c];
                } else {
                    float* pv = (float*)&v;
#pragma unroll
                    for (int i = 0; i < 4; i++) {
                        int kk = k0 + c + i;
                        pv[i] = (kk < F0) ? x[(size_t)grow * F0 + kk] : 0.f;
                    }
                }
            }
            const float* pv = (const float*)&v;
#pragma unroll
            for (int i = 0; i < 4; i++)
                split_store(&Ah[r][c + i], &Al[r][c + i], pv[i]);
        }
        // ---- load B tile 16x128 -> transposed smem [n][k] ----
#pragma unroll
        for (int i = 0; i < 8; i++) {
            int idx = tid + i * 256;
            int k = idx >> 7, n = idx & 127;
            float f = (k0 + k < F0) ? W[(size_t)(k0 + k) * F1 + n] : 0.f;
            split_store(&Bh[n][k], &Bl[n][k], f);
        }
        __syncthreads();

        // ---- fragments + MMAs ----
        unsigned ah[4], al[4];
        ah[0] = *(const unsigned*)&Ah[wm * 16 + gr][2 * ct];
        ah[1] = *(const unsigned*)&Ah[wm * 16 + gr + 8][2 * ct];
        ah[2] = *(const unsigned*)&Ah[wm * 16 + gr][2 * ct + 8];
        ah[3] = *(const unsigned*)&Ah[wm * 16 + gr + 8][2 * ct + 8];
        al[0] = *(const unsigned*)&Al[wm * 16 + gr][2 * ct];
        al[1] = *(const unsigned*)&Al[wm * 16 + gr + 8][2 * ct];
        al[2] = *(const unsigned*)&Al[wm * 16 + gr][2 * ct + 8];
        al[3] = *(const unsigned*)&Al[wm * 16 + gr + 8][2 * ct + 8];

#pragma unroll
        for (int nt = 0; nt < 8; nt++) {
            int nn = wn * 64 + nt * 8 + gr;
            unsigned bh[2], bl[2];
            bh[0] = *(const unsigned*)&Bh[nn][2 * ct];
            bh[1] = *(const unsigned*)&Bh[nn][2 * ct + 8];
            bl[0] = *(const unsigned*)&Bl[nn][2 * ct];
            bl[1] = *(const unsigned*)&Bl[nn][2 * ct + 8];
            MMA16816(d[nt], ah, bh);   // hi*hi
            MMA16816(d[nt], ah, bl);   // hi*lo
            MMA16816(d[nt], al, bh);   // lo*hi
        }
        __syncthreads();
    }

    // ---- epilogue: scale by dinv, store fp16 ----
    int r1 = row0 + wm * 16 + gr;
    int r2 = r1 + 8;
    float s1 = (r1 < N_NODES) ? g_dinv[r1] : 0.f;
    float s2 = (r2 < N_NODES) ? g_dinv[r2] : 0.f;
#pragma unroll
    for (int nt = 0; nt < 8; nt++) {
        int c = wn * 64 + nt * 8 + 2 * ct;
        if (r1 < N_NODES)
            *(__half2*)&g_y1h[(size_t)r1 * F1 + c] =
                __floats2half2_rn(d[nt][0] * s1, d[nt][1] * s1);
        if (r2 < N_NODES)
            *(__half2*)&g_y1h[(size_t)r2 * F1 + c] =
                __floats2half2_rn(d[nt][2] * s2, d[nt][3] * s2);
    }
}

// ---------------- agg 1: h = relu(dinv[d]*(y1[d] + sum y1[src]) + b1) ----------------
__global__ void k_agg1(const float* __restrict__ b) {
    int d = blockIdx.x * 8 + (threadIdx.x >> 5);
    if (d >= N_NODES) return;
    int lane = threadIdx.x & 31;
    const float2* Y = (const float2*)g_y1h;   // 32 float2 per row

    float ax[4] = {0.f, 0.f, 0.f, 0.f};
    {
        float2 r = Y[(size_t)d * 32 + lane];  // self loop
        float2 f0 = __half22float2(*(__half2*)&r.x);
        float2 f1 = __half22float2(*(__half2*)&r.y);
        ax[0] = f0.x; ax[1] = f0.y; ax[2] = f1.x; ax[3] = f1.y;
    }
    float ay[4] = {0.f, 0.f, 0.f, 0.f};
    float az[4] = {0.f, 0.f, 0.f, 0.f};
    float aw[4] = {0.f, 0.f, 0.f, 0.f};

    int j = g_off[d], end = g_off[d + 1];
    for (; j + 4 <= end; j += 4) {
        int s0 = g_csr[j], s1 = g_csr[j + 1], s2 = g_csr[j + 2], s3 = g_csr[j + 3];
        float2 r0 = Y[(size_t)s0 * 32 + lane];
        float2 r1 = Y[(size_t)s1 * 32 + lane];
        float2 r2 = Y[(size_t)s2 * 32 + lane];
        float2 r3 = Y[(size_t)s3 * 32 + lane];
        float2 f;
        f = __half22float2(*(__half2*)&r0.x); ax[0] += f.x; ax[1] += f.y;
        f = __half22float2(*(__half2*)&r0.y); ax[2] += f.x; ax[3] += f.y;
        f = __half22float2(*(__half2*)&r1.x); ay[0] += f.x; ay[1] += f.y;
        f = __half22float2(*(__half2*)&r1.y); ay[2] += f.x; ay[3] += f.y;
        f = __half22float2(*(__half2*)&r2.x); az[0] += f.x; az[1] += f.y;
        f = __half22float2(*(__half2*)&r2.y); az[2] += f.x; az[3] += f.y;
        f = __half22float2(*(__half2*)&r3.x); aw[0] += f.x; aw[1] += f.y;
        f = __half22float2(*(__half2*)&r3.y); aw[2] += f.x; aw[3] += f.y;
    }
    for (; j < end; j++) {
        float2 r = Y[(size_t)g_csr[j] * 32 + lane];
        float2 f;
        f = __half22float2(*(__half2*)&r.x); ax[0] += f.x; ax[1] += f.y;
        f = __half22float2(*(__half2*)&r.y); ax[2] += f.x; ax[3] += f.y;
    }
#pragma unroll
    for (int i = 0; i < 4; i++) ax[i] += ay[i] + az[i] + aw[i];

    float s = g_dinv[d];
    float4 bb = ((const float4*)b)[lane];
    float4 o;
    o.x = fmaxf(fmaf(ax[0], s, bb.x), 0.f);
    o.y = fmaxf(fmaf(ax[1], s, bb.y), 0.f);
    o.z = fmaxf(fmaf(ax[2], s, bb.z), 0.f);
    o.w = fmaxf(fmaf(ax[3], s, bb.w), 0.f);
    ((float4*)g_h)[(size_t)d * 32 + lane] = o;
}

// ---------------- GEMM 2: y2h = half(dinv * (h @ W2)) ----------------
__global__ void k_gemm2(const float* __restrict__ W) {
    __shared__ float As[16][64];
    __shared__ float Bs[16][64];
    const int tid = threadIdx.x;
    const int tx = tid & 15;
    const int ty = tid >> 4;
    const int row0 = blockIdx.x * 64;

    float acc[4][4];
#pragma unroll
    for (int i = 0; i < 4; i++)
#pragma unroll
        for (int j = 0; j < 4; j++) acc[i][j] = 0.f;

    for (int k0 = 0; k0 < F1; k0 += 16) {
        {
            int m = tid >> 2;
            int k = (tid & 3) * 4;
            int r = row0 + m;
            float4 v = (r < N_NODES)
                ? *(const float4*)&g_h[(size_t)r * F1 + k0 + k]
                : make_float4(0.f, 0.f, 0.f, 0.f);
            As[k][m] = v.x; As[k + 1][m] = v.y; As[k + 2][m] = v.z; As[k + 3][m] = v.w;
        }
#pragma unroll
        for (int i = 0; i < 4; i++) {
            int idx = tid + i * 256;
            Bs[idx >> 6][idx & 63] = W[(size_t)(k0 + (idx >> 6)) * F2 + (idx & 63)];
        }
        __syncthreads();
#pragma unroll
        for (int k = 0; k < 16; k++) {
            float4 av = *(const float4*)&As[k][ty * 4];
            float4 bv = *(const float4*)&Bs[k][tx * 4];
            float a[4] = {av.x, av.y, av.z, av.w};
            float b[4] = {bv.x, bv.y, bv.z, bv.w};
#pragma unroll
            for (int i = 0; i < 4; i++)
#pragma unroll
                for (int j = 0; j < 4; j++) acc[i][j] = fmaf(a[i], b[j], acc[i][j]);
        }
        __syncthreads();
    }
#pragma unroll
    for (int i = 0; i < 4; i++) {
        int r = row0 + ty * 4 + i;
        if (r < N_NODES) {
            float s = g_dinv[r];
            __half2 p0 = __floats2half2_rn(acc[i][0] * s, acc[i][1] * s);
            __half2 p1 = __floats2half2_rn(acc[i][2] * s, acc[i][3] * s);
            float2 pk;
            pk.x = __uint_as_float(*(unsigned int*)&p0);
            pk.y = __uint_as_float(*(unsigned int*)&p1);
            ((float2*)g_y2h)[((size_t)r * F2 + tx * 4) >> 2] = pk;
        }
    }
}

// ---------------- agg 2: out = dinv[d]*(y2[d] + sum y2[src]) + b2 ----------------
__global__ void k_agg2(const float* __restrict__ b, float* __restrict__ out) {
    int d = blockIdx.x * 8 + (threadIdx.x >> 5);
    if (d >= N_NODES) return;
    int lane = threadIdx.x & 31;
    const __half2* Y = (const __half2*)g_y2h;   // 32 half2 per row

    float2 a0 = __half22float2(Y[(size_t)d * 32 + lane]);  // self loop
    float2 a1 = make_float2(0.f, 0.f);
    float2 a2 = make_float2(0.f, 0.f);
    float2 a3 = make_float2(0.f, 0.f);

    int j = g_off[d], end = g_off[d + 1];
    for (; j + 4 <= end; j += 4) {
        int s0 = g_csr[j], s1 = g_csr[j + 1], s2 = g_csr[j + 2], s3 = g_csr[j + 3];
        float2 v0 = __half22float2(Y[(size_t)s0 * 32 + lane]);
        float2 v1 = __half22float2(Y[(size_t)s1 * 32 + lane]);
        float2 v2 = __half22float2(Y[(size_t)s2 * 32 + lane]);
        float2 v3 = __half22float2(Y[(size_t)s3 * 32 + lane]);
        a0.x += v0.x; a0.y += v0.y;
        a1.x += v1.x; a1.y += v1.y;
        a2.x += v2.x; a2.y += v2.y;
        a3.x += v3.x; a3.y += v3.y;
    }
    for (; j < end; j++) {
        float2 v = __half22float2(Y[(size_t)g_csr[j] * 32 + lane]);
        a0.x += v.x; a0.y += v.y;
    }
    float2 acc = make_float2(a0.x + a1.x + a2.x + a3.x,
                             a0.y + a1.y + a2.y + a3.y);
    float s = g_dinv[d];
    float2 bb = ((const float2*)b)[lane];
    acc.x = fmaf(acc.x, s, bb.x);
    acc.y = fmaf(acc.y, s, bb.y);
    ((float2*)out)[(size_t)d * 32 + lane] = acc;
}

extern "C" void kernel_launch(void* const* d_in, const int* in_sizes, int n_in,
                              void* d_out, int out_size) {
    const float* x   = (const float*)d_in[0];
    const int*   ei  = (const int*)d_in[1];
    const float* W1  = (const float*)d_in[2];
    const float* b1  = (const float*)d_in[3];
    const float* W2  = (const float*)d_in[4];
    const float* b2  = (const float*)d_in[5];
    float*       out = (float*)d_out;

    const int* src = ei;
    const int* dst = ei + N_EDGES;

    k_zero_deg<<<(N_NODES + 255) / 256, 256>>>();
    k_count<<<(N_EDGES + 255) / 256, 256>>>(dst);
    k_scan1<<<N_SCANBLK, SCAN_B>>>();
    k_scan2<<<1, 128>>>();
    k_scan3<<<N_SCANBLK, SCAN_B>>>();
    k_fill<<<(N_EDGES + 255) / 256, 256>>>(src, dst);

    k_gemm1<<<(N_NODES + 63) / 64, 256>>>(x, W1);
    k_agg1<<<(N_NODES + 7) / 8, 256>>>(b1);

    k_gemm2<<<(N_NODES + 63) / 64, 256>>>(W2);
    k_agg2<<<(N_NODES + 7) / 8, 256>>>(b2, out);
}